// round 1
// baseline (speedup 1.0000x reference)
#include <cuda_runtime.h>
#include <cuda_bf16.h>
#include <math.h>

// Problem constants
#define Nn   8
#define Cin  128
#define Cout 128
#define Hh   128
#define Ww   128
#define Kk   3
#define Ho   126
#define Wo   126
#define NTAP 9

#define PTILE 64          // pixels (wo) per block
#define KB    16          // k-chunk (channels within one tap)
#define NTHREADS 256

typedef unsigned long long ULL;

// Pre-transposed weights: [tap][c][o], o contiguous
__device__ float g_wt[NTAP * Cin * Cout];

__device__ __forceinline__ ULL pk2(float v) {
    ULL r; asm("mov.b64 %0, {%1, %1};" : "=l"(r) : "f"(v)); return r;
}
__device__ __forceinline__ void fma2(ULL &d, ULL a, ULL b) {
    asm("fma.rn.f32x2 %0, %1, %2, %0;" : "+l"(d) : "l"(a), "l"(b));
}
__device__ __forceinline__ void unpk2(ULL v, float &lo, float &hi) {
    asm("mov.b64 {%0, %1}, %2;" : "=f"(lo), "=f"(hi) : "l"(v));
}

// --------------------------------------------------------------------------
// Weight transpose: w[o][c][kh][kw]  ->  g_wt[tap][c][o]
// --------------------------------------------------------------------------
__global__ void wt_transpose_kernel(const float* __restrict__ w) {
    int idx = blockIdx.x * blockDim.x + threadIdx.x;
    if (idx >= NTAP * Cin * Cout) return;
    int o   = idx & (Cout - 1);
    int c   = (idx >> 7) & (Cin - 1);
    int tap = idx >> 14;
    g_wt[idx] = w[(o * Cin + c) * NTAP + tap];
}

// --------------------------------------------------------------------------
// Main kernel: one block = (n, ho, wo-tile of 64 pixels) x all 128 Cout.
// Implicit GEMM: k = (tap, c), 9*128 = 1152, chunked by 16.
// Thread (i = t&31, j = t>>5) owns co = 4i..4i+3, pix = 8j..8j+7
// Accumulators held as f32x2 (pixel pairs) -> packed FFMA2.
// --------------------------------------------------------------------------
__global__ void __launch_bounds__(NTHREADS, 2)
adc_main_kernel(const float* __restrict__ inp,
                const float* __restrict__ rates,
                const float* __restrict__ bias,
                float* __restrict__ out)
{
    __shared__ float  Wsm[KB * Cout];       // 8 KB
    __shared__ float  samp[KB * PTILE];     // 4 KB
    __shared__ int4   coffs[PTILE * NTAP];  // 9 KB (clamped offsets, 4 corners)
    __shared__ float4 cwts [PTILE * NTAP];  // 9 KB (masked bilinear weights)
    __shared__ float  rbuf[PTILE];          // rate per pixel

    const int t   = threadIdx.x;
    const int n   = blockIdx.z;
    const int ho  = blockIdx.y;
    const int wo0 = blockIdx.x * PTILE;

    // ---- rate map: bilinear upsample rates[32x32] -> (ho, wo0+pix) ----
    const float scale = (float)(32.0 / 126.0);
    if (t < PTILE) {
        int wo = wo0 + t;
        float sy = fminf(fmaxf(((float)ho + 0.5f) * scale - 0.5f, 0.0f), 31.0f);
        float sx = fminf(fmaxf(((float)wo + 0.5f) * scale - 0.5f, 0.0f), 31.0f);
        float y0f = floorf(sy), x0f = floorf(sx);
        int y0 = (int)y0f, x0 = (int)x0f;
        int y1 = min(y0 + 1, 31), x1 = min(x0 + 1, 31);
        float wy = sy - y0f, wx = sx - x0f;
        float r = rates[y0 * 32 + x0] * (1.0f - wy) * (1.0f - wx)
                + rates[y0 * 32 + x1] * (1.0f - wy) * wx
                + rates[y1 * 32 + x0] * wy * (1.0f - wx)
                + rates[y1 * 32 + x1] * wy * wx;
        rbuf[t] = r;
    }
    __syncthreads();

    // ---- per-(pixel, tap) gather coefficients ----
    for (int e = t; e < PTILE * NTAP; e += NTHREADS) {
        int pix = e / NTAP;
        int tap = e - pix * NTAP;
        int kh = tap / Kk, kw = tap - kh * Kk;
        int wo = wo0 + pix;
        float r = rbuf[pix];
        float fy = (float)ho + (float)kh * r;
        float fx = (float)wo + (float)kw * r;
        float y0f = floorf(fy), x0f = floorf(fx);
        float wy = fy - y0f, wx = fx - x0f;
        int y0 = (int)y0f, x0 = (int)x0f;
        int y1 = y0 + 1,   x1 = x0 + 1;
        float my0 = (y0 >= 0 && y0 < Hh) ? 1.0f : 0.0f;
        float my1 = (y1 >= 0 && y1 < Hh) ? 1.0f : 0.0f;
        float mx0 = (x0 >= 0 && x0 < Ww) ? 1.0f : 0.0f;
        float mx1 = (x1 >= 0 && x1 < Ww) ? 1.0f : 0.0f;
        float valid = (wo < Wo) ? 1.0f : 0.0f;
        float4 w4;
        w4.x = (1.0f - wy) * (1.0f - wx) * my0 * mx0 * valid;
        w4.y = (1.0f - wy) * wx          * my0 * mx1 * valid;
        w4.z = wy * (1.0f - wx)          * my1 * mx0 * valid;
        w4.w = wy * wx                   * my1 * mx1 * valid;
        int y0c = min(max(y0, 0), Hh - 1), y1c = min(max(y1, 0), Hh - 1);
        int x0c = min(max(x0, 0), Ww - 1), x1c = min(max(x1, 0), Ww - 1);
        int4 o4;
        o4.x = y0c * Ww + x0c;
        o4.y = y0c * Ww + x1c;
        o4.z = y1c * Ww + x0c;
        o4.w = y1c * Ww + x1c;
        coffs[e] = o4;
        cwts[e]  = w4;
    }
    __syncthreads();

    const int i = t & 31;     // co group (4 channels)
    const int j = t >> 5;     // pix group (8 pixels)

    // ---- accumulators: 4 co x 4 f32x2 (8 pixels), init = bias ----
    ULL acc[4][4];
    #pragma unroll
    for (int a = 0; a < 4; a++) {
        float b = bias[4 * i + a];
        ULL pb = pk2(b);
        acc[a][0] = pb; acc[a][1] = pb; acc[a][2] = pb; acc[a][3] = pb;
    }

    const int nbase = n * Cin;

    // ---- main k loop: 9 taps * 8 chunks of 16 channels ----
    for (int ch = 0; ch < NTAP * (Cin / KB); ch++) {
        int tap = ch >> 3;
        int c0  = (ch & 7) << 4;

        // stage weights (contiguous in g_wt)
        {
            const float4* src = (const float4*)(g_wt + (tap * Cin + c0) * Cout);
            float4* dst = (float4*)Wsm;
            dst[t]       = src[t];
            dst[t + 256] = src[t + 256];
        }
        // stage samples: 16 channels x 64 pixels, 4 per thread
        #pragma unroll
        for (int s = 0; s < 4; s++) {
            int e   = t + (s << 8);
            int kk  = e >> 6;
            int pix = e & 63;
            int ci  = pix * NTAP + tap;
            int4   o4 = coffs[ci];
            float4 w4 = cwts[ci];
            const float* base = inp + (((size_t)(nbase + c0 + kk)) << 14);
            float v = w4.x * __ldg(base + o4.x)
                    + w4.y * __ldg(base + o4.y)
                    + w4.z * __ldg(base + o4.z)
                    + w4.w * __ldg(base + o4.w);
            samp[(kk << 6) + pix] = v;
        }
        __syncthreads();

        // inner GEMM: 16 k-steps
        #pragma unroll
        for (int kk = 0; kk < KB; kk++) {
            float4 wv = *(const float4*)(Wsm + (kk << 7) + (i << 2));
            const ULL* sp = (const ULL*)(samp + (kk << 6) + (j << 3));
            ULL b0 = sp[0], b1 = sp[1], b2 = sp[2], b3 = sp[3];
            ULL wa = pk2(wv.x), wb = pk2(wv.y), wc = pk2(wv.z), wd = pk2(wv.w);
            fma2(acc[0][0], wa, b0); fma2(acc[0][1], wa, b1);
            fma2(acc[0][2], wa, b2); fma2(acc[0][3], wa, b3);
            fma2(acc[1][0], wb, b0); fma2(acc[1][1], wb, b1);
            fma2(acc[1][2], wb, b2); fma2(acc[1][3], wb, b3);
            fma2(acc[2][0], wc, b0); fma2(acc[2][1], wc, b1);
            fma2(acc[2][2], wc, b2); fma2(acc[2][3], wc, b3);
            fma2(acc[3][0], wd, b0); fma2(acc[3][1], wd, b1);
            fma2(acc[3][2], wd, b2); fma2(acc[3][3], wd, b3);
        }
        __syncthreads();
    }

    // ---- store: out[n][co][ho][wo0 + 8j + p] ----
    const int pixbase = wo0 + (j << 3);
    const int rem = Wo - pixbase;   // >= 6 always
    #pragma unroll
    for (int a = 0; a < 4; a++) {
        int co = 4 * i + a;
        float* orow = out + (((size_t)(n * Cout + co) * Ho + ho) * Wo) + pixbase;
        if (rem >= 8) {
            ULL* po = (ULL*)orow;   // index even -> 8B aligned
            po[0] = acc[a][0]; po[1] = acc[a][1];
            po[2] = acc[a][2]; po[3] = acc[a][3];
        } else {
            #pragma unroll
            for (int m = 0; m < 4; m++) {
                float lo, hi;
                unpk2(acc[a][m], lo, hi);
                int p = 2 * m;
                if (p     < rem) orow[p]     = lo;
                if (p + 1 < rem) orow[p + 1] = hi;
            }
        }
    }
}

// --------------------------------------------------------------------------
extern "C" void kernel_launch(void* const* d_in, const int* in_sizes, int n_in,
                              void* d_out, int out_size) {
    const float* inp   = (const float*)d_in[0];  // [8,128,128,128]
    const float* w     = (const float*)d_in[1];  // [128,128,3,3]
    const float* rates = (const float*)d_in[2];  // [1,1,32,32]
    const float* bias  = (const float*)d_in[3];  // [128]
    float* out = (float*)d_out;

    wt_transpose_kernel<<<(NTAP * Cin * Cout + 255) / 256, 256>>>(w);

    dim3 grid((Wo + PTILE - 1) / PTILE, Ho, Nn);   // (2, 126, 8)
    adc_main_kernel<<<grid, NTHREADS>>>(inp, rates, bias, out);
}

// round 6
// speedup vs baseline: 2.9346x; 2.9346x over previous
#include <cuda_runtime.h>
#include <cstdint>
#include <math.h>

#define Hh 128
#define Ww 128
#define Ho 126
#define Wo 126
#define HOWO (126*126)
#define NCH 72              // 9 taps * 8 chunks of 16 channels

// Pre-laid-out tf32 weights: per chunk [g=2][co=128][kk4=4][pair=2] = 2048 u32
__device__ uint32_t g_wt2[NCH * 2048];

__device__ __forceinline__ uint32_t smem_u32(const void* p) {
    uint32_t a;
    asm("{ .reg .u64 t; cvta.to.shared.u64 t, %1; cvt.u32.u64 %0, t; }" : "=r"(a) : "l"(p));
    return a;
}

// ---------------------------------------------------------------------------
// Weight prep: w[o][c][kh][kw] -> tf32, chunk layout matching fragment loads
// chunk ch = tap*8 + c/16 ; k-in-chunk kl = c%16 ; g=kl/8, kk=kl%8
// ---------------------------------------------------------------------------
__global__ void wt_prep(const float* __restrict__ w) {
    int id = blockIdx.x * blockDim.x + threadIdx.x;
    if (id >= 9 * 128 * 128) return;
    int o = id & 127, c = (id >> 7) & 127, tap = id >> 14;
    int ch = tap * 8 + (c >> 4);
    int kl = c & 15;
    int g = kl >> 3, kk = kl & 7, kk4 = kk & 3, h = kk >> 2;
    float v = w[(o * 128 + c) * 9 + tap];
    uint32_t u;
    asm("cvt.rna.tf32.f32 %0, %1;" : "=r"(u) : "f"(v));
    g_wt2[ch * 2048 + ((g * 128 + o) * 4 + kk4) * 2 + h] = u;
}

// ---------------------------------------------------------------------------
// Main kernel: CTA per (ho, n). D[pix 128, co 128] via mma.sync tf32.
// ---------------------------------------------------------------------------
__global__ void __launch_bounds__(256, 2)
adc_mma(const float* __restrict__ inp, const float* __restrict__ rates,
        const float* __restrict__ bias, float* __restrict__ out)
{
    __shared__ uint32_t sampS[2][2048];   // [buf][g][pix][kk4][2] (+XOR swizzle)
    __shared__ uint32_t wS[2][2048];      // [buf][g][co][kk4][2]
    __shared__ float rbuf[128];

    const int t = threadIdx.x, lane = t & 31, wrp = t >> 5;
    const int ho = blockIdx.x, n = blockIdx.y;

    // rate map: bilinear upsample rates[32x32] -> (ho, pix)
    if (t < 128) {
        const float scale = (float)(32.0 / 126.0);
        float sy = fminf(fmaxf(((float)ho + 0.5f) * scale - 0.5f, 0.0f), 31.0f);
        float sx = fminf(fmaxf(((float)t  + 0.5f) * scale - 0.5f, 0.0f), 31.0f);
        float y0f = floorf(sy), x0f = floorf(sx);
        int y0 = (int)y0f, x0 = (int)x0f;
        int y1 = min(y0 + 1, 31), x1 = min(x0 + 1, 31);
        float wy = sy - y0f, wx = sx - x0f;
        rbuf[t] = rates[y0 * 32 + x0] * (1.f - wy) * (1.f - wx)
                + rates[y0 * 32 + x1] * (1.f - wy) * wx
                + rates[y1 * 32 + x0] * wy * (1.f - wx)
                + rates[y1 * 32 + x1] * wy * wx;
    }
    __syncthreads();

    const int pix = t & 127, kg = t >> 7;
    const float rate = rbuf[pix];
    const float fvalid = (pix < Wo) ? 1.0f : 0.0f;

    // bilinear coeffs for current tap (register resident, fixed pix per thread)
    float cw0, cw1, cw2, cw3;
    int o0, o1, o2, o3;
    auto calc = [&](int tap) {
        int kh = tap / 3, kw = tap - kh * 3;
        float fy = (float)ho  + (float)kh * rate;
        float fx = (float)pix + (float)kw * rate;
        float y0f = floorf(fy), x0f = floorf(fx);
        float wy = fy - y0f, wx = fx - x0f;
        int y0 = (int)y0f, x0 = (int)x0f;
        int y1 = y0 + 1,  x1 = x0 + 1;
        float my0 = (y0 >= 0 && y0 < Hh) ? 1.f : 0.f;
        float my1 = (y1 >= 0 && y1 < Hh) ? 1.f : 0.f;
        float mx0 = (x0 >= 0 && x0 < Ww) ? 1.f : 0.f;
        float mx1 = (x1 >= 0 && x1 < Ww) ? 1.f : 0.f;
        cw0 = (1.f - wy) * (1.f - wx) * my0 * mx0 * fvalid;
        cw1 = (1.f - wy) * wx         * my0 * mx1 * fvalid;
        cw2 = wy * (1.f - wx)         * my1 * mx0 * fvalid;
        cw3 = wy * wx                 * my1 * mx1 * fvalid;
        int y0c = min(max(y0, 0), Hh - 1), y1c = min(max(y1, 0), Hh - 1);
        int x0c = min(max(x0, 0), Ww - 1), x1c = min(max(x1, 0), Ww - 1);
        o0 = y0c * Ww + x0c; o1 = y0c * Ww + x1c;
        o2 = y1c * Ww + x0c; o3 = y1c * Ww + x1c;
    };

    float v[8];
    float4 w0r, w1r;
    auto gather = [&](int ch) {
        int c0 = (ch & 7) << 4;
        const float* pl = inp + (((size_t)(n * 128 + c0 + kg * 8)) << 14);
        #pragma unroll
        for (int kk = 0; kk < 8; kk++) {
            const float* p = pl + ((size_t)kk << 14);
            v[kk] = cw0 * __ldg(p + o0) + cw1 * __ldg(p + o1)
                  + cw2 * __ldg(p + o2) + cw3 * __ldg(p + o3);
        }
        const float4* ws = (const float4*)g_wt2 + ch * 512 + t;
        w0r = __ldg(ws);
        w1r = __ldg(ws + 256);
    };

    calc(0);
    gather(0);

    // warp tile: M32 x N64 ; warps = 4 m-rows x 2 n-cols
    const int m0 = (wrp & 3) * 32, n0 = (wrp >> 2) * 64;

    // accumulators init = bias (C frag: c0=(r,c), c1=(r,c+1), c2=(r+8,c), c3=(r+8,c+1))
    float acc[2][8][4];
    #pragma unroll
    for (int ni = 0; ni < 8; ni++) {
        int cb = n0 + ni * 8 + (lane & 3) * 2;
        float b0 = __ldg(bias + cb), b1 = __ldg(bias + cb + 1);
        #pragma unroll
        for (int mi = 0; mi < 2; mi++) {
            acc[mi][ni][0] = b0; acc[mi][ni][1] = b1;
            acc[mi][ni][2] = b0; acc[mi][ni][3] = b1;
        }
    }

    const uint32_t sa = smem_u32(sampS), wa = smem_u32(wS);
    const uint32_t srow = (uint32_t)(kg * 128 + pix) * 32;
    const uint32_t xorv = (pix & 4) << 2;    // 16B-half XOR swizzle

    for (int ch = 0; ch < NCH; ch++) {
        const int st = ch & 1;
        const uint32_t sbase = sa + st * 8192;
        const uint32_t wbase = wa + st * 8192;

        // ---- STS gathered samples (tf32) + weights ----
        {
            uint32_t u[8];
            #pragma unroll
            for (int kk = 0; kk < 8; kk++)
                asm("cvt.rna.tf32.f32 %0, %1;" : "=r"(u[kk]) : "f"(v[kk]));
            uint32_t a1 = sbase + srow + xorv;
            uint32_t a2 = sbase + srow + (16u ^ xorv);
            asm volatile("st.shared.v4.b32 [%0], {%1,%2,%3,%4};"
                         :: "r"(a1), "r"(u[0]), "r"(u[4]), "r"(u[1]), "r"(u[5]));
            asm volatile("st.shared.v4.b32 [%0], {%1,%2,%3,%4};"
                         :: "r"(a2), "r"(u[2]), "r"(u[6]), "r"(u[3]), "r"(u[7]));
            float4* wd = (float4*)(wS[st]);
            wd[t] = w0r;
            wd[t + 256] = w1r;
        }
        __syncthreads();

        // ---- gather next chunk (overlaps MMA across warps) ----
        if (ch < NCH - 1) {
            int c1 = ch + 1;
            if ((c1 & 7) == 0) calc(c1 >> 3);
            gather(c1);
        }

        // ---- MMA: 2 k8-groups x (2 m16 x 8 n8) ----
        #pragma unroll
        for (int g = 0; g < 2; g++) {
            const uint32_t ab = sbase + (uint32_t)g * 4096;
            const uint32_t bb = wbase + (uint32_t)g * 4096;
            const uint32_t k8off = (lane & 3) * 8;
            uint32_t A[2][4];
            #pragma unroll
            for (int mi = 0; mi < 2; mi++) {
                int r0 = m0 + mi * 16 + (lane >> 2);
                int r1 = r0 + 8;
                uint32_t ad0 = ab + (uint32_t)r0 * 32 + (k8off ^ ((r0 & 4) << 2));
                uint32_t ad1 = ab + (uint32_t)r1 * 32 + (k8off ^ ((r1 & 4) << 2));
                asm volatile("ld.shared.v2.b32 {%0,%1}, [%2];"
                             : "=r"(A[mi][0]), "=r"(A[mi][2]) : "r"(ad0));
                asm volatile("ld.shared.v2.b32 {%0,%1}, [%2];"
                             : "=r"(A[mi][1]), "=r"(A[mi][3]) : "r"(ad1));
            }
            #pragma unroll
            for (int ni = 0; ni < 8; ni++) {
                int co = n0 + ni * 8 + (lane >> 2);
                uint32_t bd = bb + (uint32_t)co * 32 + k8off;
                uint32_t B0, B1;
                asm volatile("ld.shared.v2.b32 {%0,%1}, [%2];"
                             : "=r"(B0), "=r"(B1) : "r"(bd));
                #pragma unroll
                for (int mi = 0; mi < 2; mi++) {
                    asm volatile(
                        "mma.sync.aligned.m16n8k8.row.col.f32.tf32.tf32.f32 "
                        "{%0,%1,%2,%3}, {%4,%5,%6,%7}, {%8,%9}, {%0,%1,%2,%3};"
                        : "+f"(acc[mi][ni][0]), "+f"(acc[mi][ni][1]),
                          "+f"(acc[mi][ni][2]), "+f"(acc[mi][ni][3])
                        : "r"(A[mi][0]), "r"(A[mi][1]), "r"(A[mi][2]), "r"(A[mi][3]),
                          "r"(B0), "r"(B1));
                }
            }
        }
        __syncthreads();
    }

    // ---- epilogue: scatter C frags to out[n][co][ho][wo] ----
    #pragma unroll
    for (int mi = 0; mi < 2; mi++) {
        int r0 = m0 + mi * 16 + (lane >> 2);
        int r1 = r0 + 8;
        #pragma unroll
        for (int ni = 0; ni < 8; ni++) {
            int co = n0 + ni * 8 + (lane & 3) * 2;
            float* p0 = out + (size_t)(n * 128 + co) * HOWO + ho * Wo;
            float* p1 = p0 + HOWO;
            if (r0 < Wo) { p0[r0] = acc[mi][ni][0]; p1[r0] = acc[mi][ni][1]; }
            if (r1 < Wo) { p0[r1] = acc[mi][ni][2]; p1[r1] = acc[mi][ni][3]; }
        }
    }
}

// ---------------------------------------------------------------------------
extern "C" void kernel_launch(void* const* d_in, const int* in_sizes, int n_in,
                              void* d_out, int out_size) {
    const float* inp   = (const float*)d_in[0];  // [8,128,128,128]
    const float* wgt   = (const float*)d_in[1];  // [128,128,3,3]
    const float* rates = (const float*)d_in[2];  // [1,1,32,32]
    const float* bias  = (const float*)d_in[3];  // [128]
    float* out = (float*)d_out;

    wt_prep<<<(9 * 128 * 128 + 255) / 256, 256>>>(wgt);

    dim3 grid(Ho, 8);   // (126, 8) = 1008 CTAs
    adc_mma<<<grid, 256>>>(inp, rates, bias, out);
}

// round 8
// speedup vs baseline: 3.9260x; 1.3378x over previous
#include <cuda_runtime.h>
#include <cuda_fp16.h>
#include <cstdint>
#include <math.h>

#define Hh 128
#define Ww 128
#define Ho 126
#define Wo 126
#define HOWO (126*126)
#define NCH 36              // 9 taps * 4 chunks of 32 channels

// fp16 weights, fragment-interleaved: [ch][g][co][slot u16 x16]
// slot S (u32 granularity, 8 per row): S even -> k{S,S+1}, S odd -> k{S+7,S+8}
__device__ __half g_wt[NCH * 2 * 128 * 16];

__device__ __forceinline__ uint32_t smem_u32(const void* p) {
    uint32_t a;
    asm("{ .reg .u64 t; cvta.to.shared.u64 t, %1; cvt.u32.u64 %0, t; }" : "=r"(a) : "l"(p));
    return a;
}

// ---------------------------------------------------------------------------
// Weight prep: w[o][c][kh][kw] -> fp16, interleaved fragment layout
// ---------------------------------------------------------------------------
__global__ void wt_prep(const float* __restrict__ w) {
    int id = blockIdx.x * blockDim.x + threadIdx.x;
    if (id >= 9 * 128 * 128) return;
    int o = id & 127, c = (id >> 7) & 127, tap = id >> 14;
    int ch = tap * 4 + (c >> 5);
    int g  = (c >> 4) & 1;
    int k  = c & 15;
    int S    = (k < 8) ? (k & ~1) : (((k - 8) & ~1) + 1);
    int half = k & 1;
    float v = w[(o * 128 + c) * 9 + tap];
    g_wt[(((ch * 2 + g) * 128 + o) * 16) + S * 2 + half] = __float2half_rn(v);
}

// ---------------------------------------------------------------------------
// Main kernel: CTA per (ho, n). D[pix 128, co 128] via mma.sync fp16 m16n8k16.
// ---------------------------------------------------------------------------
__global__ void __launch_bounds__(256, 2)
adc_mma(const float* __restrict__ inp, const float* __restrict__ rates,
        const float* __restrict__ bias, float* __restrict__ out)
{
    __shared__ uint32_t sampS[2][2][128][8];   // [buf][g][pix][8 u32] fp16 pairs
    __shared__ uint32_t wS[2][2][128][8];      // [buf][g][co][8 u32]
    __shared__ float rbuf[128];

    const int t = threadIdx.x, lane = t & 31, wrp = t >> 5;
    const int ho = blockIdx.x, n = blockIdx.y;

    // rate map: bilinear upsample rates[32x32] -> (ho, pix)
    if (t < 128) {
        const float scale = (float)(32.0 / 126.0);
        float sy = fminf(fmaxf(((float)ho + 0.5f) * scale - 0.5f, 0.0f), 31.0f);
        float sx = fminf(fmaxf(((float)t  + 0.5f) * scale - 0.5f, 0.0f), 31.0f);
        float y0f = floorf(sy), x0f = floorf(sx);
        int y0 = (int)y0f, x0 = (int)x0f;
        int y1 = min(y0 + 1, 31), x1 = min(x0 + 1, 31);
        float wy = sy - y0f, wx = sx - x0f;
        rbuf[t] = rates[y0 * 32 + x0] * (1.f - wy) * (1.f - wx)
                + rates[y0 * 32 + x1] * (1.f - wy) * wx
                + rates[y1 * 32 + x0] * wy * (1.f - wx)
                + rates[y1 * 32 + x1] * wy * wx;
    }
    __syncthreads();

    const int pix = t & 127, kg = t >> 7;
    const float rate = rbuf[pix];
    const float fvalid = (pix < Wo) ? 1.0f : 0.0f;

    // bilinear coeffs for current tap (register resident, fixed pix per thread)
    float cw0, cw1, cw2, cw3;
    int o0, o1, o2, o3;
    auto calc = [&](int tap) {
        int kh = tap / 3, kw = tap - kh * 3;
        float fy = (float)ho  + (float)kh * rate;
        float fx = (float)pix + (float)kw * rate;
        float y0f = floorf(fy), x0f = floorf(fx);
        float wy = fy - y0f, wx = fx - x0f;
        int y0 = (int)y0f, x0 = (int)x0f;
        int y1 = y0 + 1,  x1 = x0 + 1;
        float my0 = (y0 >= 0 && y0 < Hh) ? 1.f : 0.f;
        float my1 = (y1 >= 0 && y1 < Hh) ? 1.f : 0.f;
        float mx0 = (x0 >= 0 && x0 < Ww) ? 1.f : 0.f;
        float mx1 = (x1 >= 0 && x1 < Ww) ? 1.f : 0.f;
        cw0 = (1.f - wy) * (1.f - wx) * my0 * mx0 * fvalid;
        cw1 = (1.f - wy) * wx         * my0 * mx1 * fvalid;
        cw2 = wy * (1.f - wx)         * my1 * mx0 * fvalid;
        cw3 = wy * wx                 * my1 * mx1 * fvalid;
        int y0c = min(max(y0, 0), Hh - 1), y1c = min(max(y1, 0), Hh - 1);
        int x0c = min(max(x0, 0), Ww - 1), x1c = min(max(x1, 0), Ww - 1);
        o0 = y0c * Ww + x0c; o1 = y0c * Ww + x1c;
        o2 = y1c * Ww + x0c; o3 = y1c * Ww + x1c;
    };

    uint32_t ug[2][4];      // gathered fp16x2 slots, per g group
    float4 w0r, w1r;        // weight chunk prefetch
    auto gather = [&](int ch) {
        const int cb = n * 128 + (ch & 3) * 32;
        #pragma unroll
        for (int g = 0; g < 2; g++) {
            const float* pg = inp + ((size_t)(cb + g * 16) << 14);
            #pragma unroll
            for (int s = 0; s < 4; s++) {
                int S  = 4 * kg + s;
                int kA = (S & 1) ? (S + 7) : S;
                const float* p = pg + ((size_t)kA << 14);
                float e = cw0 * __ldg(p + o0) + cw1 * __ldg(p + o1)
                        + cw2 * __ldg(p + o2) + cw3 * __ldg(p + o3);
                const float* q = p + 16384;
                float od = cw0 * __ldg(q + o0) + cw1 * __ldg(q + o1)
                         + cw2 * __ldg(q + o2) + cw3 * __ldg(q + o3);
                asm("cvt.rn.f16x2.f32 %0, %1, %2;" : "=r"(ug[g][s]) : "f"(od), "f"(e));
            }
        }
        const float4* ws = (const float4*)g_wt + ch * 512 + t;
        w0r = __ldg(ws);
        w1r = __ldg(ws + 256);
    };

    calc(0);
    gather(0);

    // warp tile: M32 x N64 ; warps = 4 m-rows x 2 n-cols
    const int m0 = (wrp & 3) * 32, n0 = (wrp >> 2) * 64;

    // accumulators init = bias (C frag: c0=(r,c), c1=(r,c+1), c2=(r+8,c), c3=(r+8,c+1))
    float acc[2][8][4];
    #pragma unroll
    for (int ni = 0; ni < 8; ni++) {
        int cb = n0 + ni * 8 + (lane & 3) * 2;
        float b0 = __ldg(bias + cb), b1 = __ldg(bias + cb + 1);
        #pragma unroll
        for (int mi = 0; mi < 2; mi++) {
            acc[mi][ni][0] = b0; acc[mi][ni][1] = b1;
            acc[mi][ni][2] = b0; acc[mi][ni][3] = b1;
        }
    }

    const uint32_t sa = smem_u32(sampS), wa = smem_u32(wS);
    const uint32_t xorv = (pix & 4) << 2;    // 16B-half XOR swizzle (samp only)

    for (int ch = 0; ch < NCH; ch++) {
        const int st = ch & 1;
        const uint32_t sbase = sa + st * 8192;
        const uint32_t wbase = wa + st * 8192;

        // ---- STS gathered fp16 samples + weights ----
        {
            #pragma unroll
            for (int g = 0; g < 2; g++) {
                uint32_t a1 = sbase + (uint32_t)(g * 128 + pix) * 32
                            + ((uint32_t)(kg * 16) ^ xorv);
                asm volatile("st.shared.v4.b32 [%0], {%1,%2,%3,%4};"
                             :: "r"(a1), "r"(ug[g][0]), "r"(ug[g][1]),
                                "r"(ug[g][2]), "r"(ug[g][3]));
            }
            float4* wd = (float4*)(wS[st]);
            wd[t] = w0r;
            wd[t + 256] = w1r;
        }
        __syncthreads();

        // ---- gather next chunk (overlaps MMA across warps) ----
        if (ch < NCH - 1) {
            int c1 = ch + 1;
            if ((c1 & 3) == 0) calc(c1 >> 2);
            gather(c1);
        }

        // ---- MMA: 2 k16-groups x (2 m16 x 8 n8) ----
        #pragma unroll
        for (int g = 0; g < 2; g++) {
            const uint32_t ab = sbase + (uint32_t)g * 4096;
            const uint32_t bb = wbase + (uint32_t)g * 4096;
            const uint32_t k8off = (lane & 3) * 8;
            uint32_t A[2][4];
            #pragma unroll
            for (int mi = 0; mi < 2; mi++) {
                int r0 = m0 + mi * 16 + (lane >> 2);
                int r1 = r0 + 8;
                uint32_t ad0 = ab + (uint32_t)r0 * 32 + (k8off ^ ((r0 & 4) << 2));
                uint32_t ad1 = ab + (uint32_t)r1 * 32 + (k8off ^ ((r1 & 4) << 2));
                asm volatile("ld.shared.v2.b32 {%0,%1}, [%2];"
                             : "=r"(A[mi][0]), "=r"(A[mi][2]) : "r"(ad0));
                asm volatile("ld.shared.v2.b32 {%0,%1}, [%2];"
                             : "=r"(A[mi][1]), "=r"(A[mi][3]) : "r"(ad1));
            }
            #pragma unroll
            for (int ni = 0; ni < 8; ni++) {
                int co = n0 + ni * 8 + (lane >> 2);
                uint32_t bd = bb + (uint32_t)co * 32 + k8off;
                uint32_t B0, B1;
                asm volatile("ld.shared.v2.b32 {%0,%1}, [%2];"
                             : "=r"(B0), "=r"(B1) : "r"(bd));
                #pragma unroll
                for (int mi = 0; mi < 2; mi++) {
                    asm volatile(
                        "mma.sync.aligned.m16n8k16.row.col.f32.f16.f16.f32 "
                        "{%0,%1,%2,%3}, {%4,%5,%6,%7}, {%8,%9}, {%0,%1,%2,%3};"
                        : "+f"(acc[mi][ni][0]), "+f"(acc[mi][ni][1]),
                          "+f"(acc[mi][ni][2]), "+f"(acc[mi][ni][3])
                        : "r"(A[mi][0]), "r"(A[mi][1]), "r"(A[mi][2]), "r"(A[mi][3]),
                          "r"(B0), "r"(B1));
                }
            }
        }
        __syncthreads();
    }

    // ---- epilogue: scatter C frags to out[n][co][ho][wo] ----
    #pragma unroll
    for (int mi = 0; mi < 2; mi++) {
        int r0 = m0 + mi * 16 + (lane >> 2);
        int r1 = r0 + 8;
        #pragma unroll
        for (int ni = 0; ni < 8; ni++) {
            int co = n0 + ni * 8 + (lane & 3) * 2;
            float* p0 = out + (size_t)(n * 128 + co) * HOWO + ho * Wo;
            float* p1 = p0 + HOWO;
            if (r0 < Wo) { p0[r0] = acc[mi][ni][0]; p1[r0] = acc[mi][ni][1]; }
            if (r1 < Wo) { p0[r1] = acc[mi][ni][2]; p1[r1] = acc[mi][ni][3]; }
        }
    }
}

// ---------------------------------------------------------------------------
extern "C" void kernel_launch(void* const* d_in, const int* in_sizes, int n_in,
                              void* d_out, int out_size) {
    const float* inp   = (const float*)d_in[0];  // [8,128,128,128]
    const float* wgt   = (const float*)d_in[1];  // [128,128,3,3]
    const float* rates = (const float*)d_in[2];  // [1,1,32,32]
    const float* bias  = (const float*)d_in[3];  // [128]
    float* out = (float*)d_out;

    wt_prep<<<(9 * 128 * 128 + 255) / 256, 256>>>(wgt);

    dim3 grid(Ho, 8);   // (126, 8) = 1008 CTAs
    adc_mma<<<grid, 256>>>(inp, rates, bias, out);
}